// round 17
// baseline (speedup 1.0000x reference)
#include <cuda_runtime.h>
#include <cfloat>

// PoolingLayer: out[p, f] = max_k features[neighbor_indices[p, k], f]
// N=100000, NP=50000, K=32, F=128
// Inputs: points (N,3) f32 [unused], features (N,128) f32,
//         neighbor_indices (NP,32) int32. Output (NP,128) f32.
//
// LTS-bound random gather at the L2 service plateau (noise band 45.3-48.2us
// for identical code). This round: PERSISTENT grid-stride launch. Previous
// launches used 6250 CTAs (~12 waves at 3.5 CTAs/SM); each wave transition
// costs ~2360cyc plus per-wave tail imbalance (cross-CTA L1tex-queue spread).
// A persistent grid (152 SMs x 4 CTAs, each warp loops over ~10 points)
// collapses this to a single wave, amortizing tail imbalance into one final
// iteration. Gather body is the proven R12 form verbatim:
// one warp per point; lane = 32-byte slot; 16 lanes span a 512B row; one
// ld.global.v8 (LDG.256) fetches TWO neighbor rows; cross-half max via
// shfl_xor(16); output stored with st.global.cs (evict-first).

#define NPTS   100000
#define NP_OUT 50000
#define KNBR   32
#define FDIM   128            // 512 bytes per feature row

#define GRID_CTAS 608          // 152 SMs x 4 CTAs
#define BLOCK_THREADS 256      // 8 warps per CTA

__device__ __forceinline__ void ldg256(const char* p, float* v) {
    asm volatile("ld.global.v8.f32 {%0,%1,%2,%3,%4,%5,%6,%7}, [%8];"
                 : "=f"(v[0]), "=f"(v[1]), "=f"(v[2]), "=f"(v[3]),
                   "=f"(v[4]), "=f"(v[5]), "=f"(v[6]), "=f"(v[7])
                 : "l"(p));
}

__device__ __forceinline__ void stg256_cs(char* p, const float* v) {
    asm volatile("st.global.cs.v8.f32 [%0], {%1,%2,%3,%4,%5,%6,%7,%8};"
                 :: "l"(p),
                    "f"(v[0]), "f"(v[1]), "f"(v[2]), "f"(v[3]),
                    "f"(v[4]), "f"(v[5]), "f"(v[6]), "f"(v[7])
                 : "memory");
}

__global__ __launch_bounds__(BLOCK_THREADS)
void pool_max_kernel(const char* __restrict__ feats_b,   // features base (bytes)
                     const int* __restrict__ nbr,        // (NP, 32) int32
                     char* __restrict__ out_b)            // (NP, 128) f32 (bytes)
{
    const int lane = threadIdx.x & 31;
    const int warp0 = (blockIdx.x * BLOCK_THREADS + threadIdx.x) >> 5;
    const int nwarps = (GRID_CTAS * BLOCK_THREADS) >> 5;   // 4864 warps

    const int half = lane >> 4;          // 0: even rows, 1: odd rows
    const int m    = lane & 15;          // 32-byte slot within the row
    const char* base = feats_b + (m << 5);   // + slot*32 bytes

    // Persistent grid-stride loop: one warp handles ~NP/nwarps points.
    for (int point = warp0; point < NP_OUT; point += nwarps) {
        // Coalesced load of the 32 neighbor indices, pre-scaled to byte offsets.
        const int my_idx = nbr[(size_t)point * KNBR + lane];
        const int my_off = my_idx << 9;      // *512 bytes per row

        float acc[8];
        #pragma unroll
        for (int j = 0; j < 8; j++) acc[j] = -FLT_MAX;

        // 32 neighbors, 4 rows per batch via 2 LDG.256 in flight.
        #pragma unroll
        for (int k = 0; k < KNBR; k += 4) {
            const int oA = __shfl_sync(0xffffffffu, my_off, k + half);      // rows k / k+1
            const int oB = __shfl_sync(0xffffffffu, my_off, k + 2 + half);  // rows k+2 / k+3
            float va[8], vb[8];
            ldg256(base + oA, va);
            ldg256(base + oB, vb);
            #pragma unroll
            for (int j = 0; j < 8; j++)
                acc[j] = fmaxf(acc[j], fmaxf(va[j], vb[j]));
        }

        // Combine even-row half with odd-row half: the same column slot lives
        // in lane m and lane m+16.
        #pragma unroll
        for (int j = 0; j < 8; j++) {
            const float o = __shfl_xor_sync(0xffffffffu, acc[j], 16);
            acc[j] = fmaxf(acc[j], o);
        }

        // Lanes 0..15 write the 512B output row with STG.256 (evict-first).
        if (half == 0) {
            stg256_cs(out_b + (size_t)point * (FDIM * 4) + (m << 5), acc);
        }
    }
}

extern "C" void kernel_launch(void* const* d_in, const int* in_sizes, int n_in,
                              void* d_out, int out_size) {
    // d_in[0] = points (unused), d_in[1] = features, d_in[2] = neighbor_indices
    const char* feats = (const char*)d_in[1];
    const int* nbr = (const int*)d_in[2];
    char* out = (char*)d_out;

    pool_max_kernel<<<GRID_CTAS, BLOCK_THREADS>>>(feats, nbr, out);
}